// round 14
// baseline (speedup 1.0000x reference)
#include <cuda_runtime.h>
#include <math.h>
#include <stdint.h>

// Problem constants
#define NB 128   // batch
#define TS 512   // timesteps
#define DI 512   // input dim
#define HD 512   // hidden dim

typedef unsigned long long ull;

// ---------------- packed f32x2 helpers (sm_100+ FFMA2 path) ----------------
__device__ __forceinline__ void fma2(ull& acc, ull a, ull b) {
    asm("fma.rn.f32x2 %0, %1, %2, %0;" : "+l"(acc) : "l"(a), "l"(b));
}
__device__ __forceinline__ void add2(ull& a, ull b) {
    asm("add.rn.f32x2 %0, %0, %1;" : "+l"(a) : "l"(b));
}
__device__ __forceinline__ void unpack2(ull v, float& lo, float& hi) {
    unsigned int a, b;
    asm("mov.b64 {%0, %1}, %2;" : "=r"(a), "=r"(b) : "l"(v));
    lo = __uint_as_float(a);
    hi = __uint_as_float(b);
}
__device__ __forceinline__ ull pack_dup(uint32_t h) {
    ull r;
    asm("mov.b64 %0, {%1, %1};" : "=l"(r) : "r"(h));
    return r;
}

#define CLUSTER_ARRIVE() asm volatile("barrier.cluster.arrive.aligned;" ::: "memory")
#define CLUSTER_WAIT()   asm volatile("barrier.cluster.wait.aligned;" ::: "memory")

__device__ __forceinline__ uint32_t smem_u32(const void* p) {
    uint32_t a;
    asm("{ .reg .u64 t; cvta.to.shared.u64 t, %1; cvt.u32.u64 %0, t; }"
        : "=r"(a) : "l"(p));
    return a;
}
__device__ __forceinline__ uint32_t mapa_rank(uint32_t laddr, uint32_t rank) {
    uint32_t r;
    asm("mapa.shared::cluster.u32 %0, %1, %2;" : "=r"(r) : "r"(laddr), "r"(rank));
    return r;
}
__device__ __forceinline__ uint4 ld_cluster_v4(uint32_t addr) {
    uint4 v;
    asm volatile("ld.shared::cluster.v4.b32 {%0,%1,%2,%3}, [%4];"
                 : "=r"(v.x), "=r"(v.y), "=r"(v.z), "=r"(v.w) : "r"(addr));
    return v;
}

// ---------------------------------------------------------------------------
// Kernel 1: xW = x @ Wx + b  (unchanged — proven, rel_err 3.7e-7)
// ---------------------------------------------------------------------------
__global__ __launch_bounds__(256) void xw_gemm(
    const float* __restrict__ A,
    const float* __restrict__ B,
    const float* __restrict__ bias,
    float* __restrict__ C)
{
    __shared__ float2 As2[128][16];
    __shared__ float  Bs[16][128];

    const int m0  = blockIdx.y * 128;
    const int n0  = blockIdx.x * 128;
    const int tid = threadIdx.x;
    const int tn  = tid & 15;
    const int tm  = tid >> 4;

    ull acc[8][4];
#pragma unroll
    for (int i = 0; i < 8; i++)
#pragma unroll
        for (int j = 0; j < 4; j++) acc[i][j] = 0ULL;

    for (int k0 = 0; k0 < DI; k0 += 16) {
#pragma unroll
        for (int j = 0; j < 2; j++) {
            int f  = tid + j * 256;
            int m  = f >> 2;
            int kq = f & 3;
            float4 v = *(const float4*)(A + (size_t)(m0 + m) * DI + k0 + kq * 4);
            *(float4*)(&As2[m][kq * 4])     = make_float4(v.x, v.x, v.y, v.y);
            *(float4*)(&As2[m][kq * 4 + 2]) = make_float4(v.z, v.z, v.w, v.w);
        }
#pragma unroll
        for (int j = 0; j < 2; j++) {
            int f  = tid + j * 256;
            int k  = f >> 5;
            int nq = f & 31;
            *(float4*)(&Bs[k][nq * 4]) =
                *(const float4*)(B + (size_t)(k0 + k) * HD + n0 + nq * 4);
        }
        __syncthreads();

#pragma unroll
        for (int k = 0; k < 16; k++) {
            ulonglong2 b01 = *(const ulonglong2*)(&Bs[k][tn * 8]);
            ulonglong2 b23 = *(const ulonglong2*)(&Bs[k][tn * 8 + 4]);
#pragma unroll
            for (int i = 0; i < 8; i++) {
                ull a = *(const ull*)(&As2[tm * 8 + i][k]);
                fma2(acc[i][0], a, b01.x);
                fma2(acc[i][1], a, b01.y);
                fma2(acc[i][2], a, b23.x);
                fma2(acc[i][3], a, b23.y);
            }
        }
        __syncthreads();
    }

    const float4 bb0 = *(const float4*)(bias + n0 + tn * 8);
    const float4 bb1 = *(const float4*)(bias + n0 + tn * 8 + 4);
#pragma unroll
    for (int i = 0; i < 8; i++) {
        float r0, r1, r2, r3, r4, r5, r6, r7;
        unpack2(acc[i][0], r0, r1);
        unpack2(acc[i][1], r2, r3);
        unpack2(acc[i][2], r4, r5);
        unpack2(acc[i][3], r6, r7);
        float* p = C + (size_t)(m0 + tm * 8 + i) * HD + n0 + tn * 8;
        *(float4*)p       = make_float4(r0 + bb0.x, r1 + bb0.y, r2 + bb0.z, r3 + bb0.w);
        *(float4*)(p + 4) = make_float4(r4 + bb1.x, r5 + bb1.y, r6 + bb1.z, r7 + bb1.w);
    }
}

// ---------------------------------------------------------------------------
// Kernel 2: persistent recurrence — 512 threads (16 warps) for latency hiding.
//
// Grid: 16 clusters x 8 CTAs. Cluster y: rows [8y,8y+8); CTA x: cols [64x,+64).
// Wh slice [512][64] smem-resident (oct-major, 16400B stride — R13-proven).
// Hs: raw f32 h rows, stride 2072 (rh offset 24 banks, ksl offset 16 banks ->
// the 4 distinct h addresses per LDS.32 hit 4 distinct banks: 1 phase).
//
// Thread (ksl=tid>>4, rh=(tid>>3)&1, co=tid&7): 4 rows x 8 cols over 16 k.
// Per kk: 4 LDS.32 + 4 pack + 2 LDS.128 + 16 FFMA2.
//
// Reduction (two-stage, all 512 threads):
//   dump: 16 STS.64 to RED[(co+8j+32i+128rh)*272 + ((ksl+8rh)&31)*8]
//         (within-phase banks = 4co+16rh+const: 16 distinct -> 2 phases)
//   stage1: thread u sums 16 partials of slot u>>1, half u&1 -> RED2[u]
//   stage2: thread u<256 adds the 2 halves, + xw, tanh, STG, raw export.
// Exchange: ARRIVE -> prefetch next xw LDG -> WAIT -> mapa pull (skipped on
// final step: exit hazard) -> sync. Export double-buffered (2KB raw).
// ---------------------------------------------------------------------------
#define HR       2072
#define WS_OFF   0
#define WOCT     16400
#define HS_OFF   131200                       // 8*16400
#define EXP_OFF  (HS_OFF + 8 * HR)            // 147776
#define RED_OFF  (EXP_OFF + 2 * 2048)         // 151872
#define RED2_OFF (RED_OFF + 256 * 272)        // 221504
#define SMEM_RNN_BYTES (RED2_OFF + 4096)      // 225600

__global__ __launch_bounds__(512, 1) __cluster_dims__(8, 1, 1)
void rnn_persistent(const float* __restrict__ Wh,
                    const float* __restrict__ h0,
                    float* __restrict__ out)
{
    extern __shared__ char smem[];
    const uint32_t sbase = smem_u32(smem);

    const int tid = threadIdx.x;
    const int m0  = blockIdx.y * 8;
    const int n0  = blockIdx.x * 64;

    // ---- load Wh slice once (oct-major): 8192 float4, 16/thread ----
#pragma unroll 4
    for (int j = 0; j < 16; j++) {
        int f   = tid + j * 512;
        int k   = f >> 4;
        int nq  = f & 15;
        int oct = nq >> 1;
        int hf  = nq & 1;
        *(float4*)(smem + WS_OFF + (size_t)oct * WOCT + k * 32 + hf * 16) =
            *(const float4*)(Wh + (size_t)k * HD + n0 + nq * 4);
    }
    // ---- stage h0 (raw): 2048 float2, 4/thread ----
#pragma unroll
    for (int j = 0; j < 4; j++) {
        int f   = tid + j * 512;
        int row = f >> 8;
        int q   = f & 255;
        *(float2*)(smem + HS_OFF + row * HR + q * 8) =
            *(const float2*)(h0 + (size_t)(m0 + row) * HD + q * 2);
    }
    __syncthreads();

    // compute decomposition
    const int ksl = tid >> 4;          // 0..31, k in [16ksl, 16ksl+16)
    const int rh  = (tid >> 3) & 1;    // rows rh*4 .. rh*4+3
    const int co  = tid & 7;           // cols co*8 .. co*8+7

    const char* hb = smem + HS_OFF + rh * 4 * HR + ksl * 64;
    const char* wb = smem + WS_OFF + (size_t)co * WOCT + ksl * 512;

    // dump base (per-acc offsets: +j*2176, +i*8704)
    char* dbase = smem + RED_OFF + (size_t)(co + 128 * rh) * 272
                  + (((ksl + 8 * rh) & 31) << 3);

    // stage1 mapping: thread u -> slot u>>1, half u&1
    const int s1s  = tid >> 1;
    const int s1hf = tid & 1;
    const int s1r  = s1s >> 5, s1cp = s1s & 31;
    const int s1rh = s1r >> 2, s1i = s1r & 3;
    const int s1co = s1cp >> 2, s1j = s1cp & 3;
    const char* s1base = smem + RED_OFF
        + (size_t)(s1co + 8 * s1j + 32 * s1i + 128 * s1rh) * 272;
    const int c0 = (s1hf * 16 + 8 * s1rh) & 31;

    // epilogue slot (tid<256): row er, colpair ecp
    const int er  = tid >> 5;
    const int ecp = tid & 31;
    float* pio = out + (size_t)(m0 + er) * TS * HD + n0 + ecp * 2;
    float2 xw_cur = make_float2(0.f, 0.f);
    if (tid < 256) xw_cur = *(const float2*)pio;

    // pull mapping: 2 warps per rank; warp covers 4 rows x 8 parts of 32B
    const int pwarp = tid >> 5;
    const int lane  = tid & 31;
    const int prank = pwarp >> 1;
    const int phf   = pwarp & 1;
    const int prow  = phf * 4 + (lane >> 3);
    const int ppart = lane & 7;
    char* pd = smem + HS_OFF + prow * HR + prank * 256 + ppart * 32;

    for (int t = 0; t < TS; t++) {
        // ---- 4x8 register-blocked partial GEMM over 16 k ----
        ull acc[4][4];
#pragma unroll
        for (int i = 0; i < 4; i++)
#pragma unroll
            for (int j = 0; j < 4; j++) acc[i][j] = 0ULL;

#pragma unroll
        for (int kk = 0; kk < 16; kk++) {
            ull hp[4];
#pragma unroll
            for (int i = 0; i < 4; i++)
                hp[i] = pack_dup(*(const uint32_t*)(hb + i * HR + kk * 4));
            ulonglong2 wA = *(const ulonglong2*)(wb + kk * 32);
            ulonglong2 wB = *(const ulonglong2*)(wb + kk * 32 + 16);
#pragma unroll
            for (int i = 0; i < 4; i++) {
                fma2(acc[i][0], hp[i], wA.x);
                fma2(acc[i][1], hp[i], wA.y);
                fma2(acc[i][2], hp[i], wB.x);
                fma2(acc[i][3], hp[i], wB.y);
            }
        }

        // ---- dump 16 partials (2-phase clean STS.64) ----
#pragma unroll
        for (int i = 0; i < 4; i++)
#pragma unroll
            for (int j = 0; j < 4; j++)
                *(ull*)(dbase + i * 8704 + j * 2176) = acc[i][j];
        __syncthreads();

        // ---- stage1: half-sum of 16 partials -> RED2[tid] ----
        {
            ull s = *(const ull*)(s1base + (((c0 + 0) & 31) << 3));
#pragma unroll
            for (int q = 1; q < 16; q++)
                add2(s, *(const ull*)(s1base + (((c0 + q) & 31) << 3)));
            *(ull*)(smem + RED2_OFF + tid * 8) = s;
        }
        __syncthreads();

        // ---- stage2 + epilogue (tid<256) ----
        if (tid < 256) {
            ulonglong2 v = *(const ulonglong2*)(smem + RED2_OFF + tid * 16);
            add2(v.x, v.y);
            float slo, shi;
            unpack2(v.x, slo, shi);
            float2 hv;
            hv.x = tanhf(xw_cur.x + slo);
            hv.y = tanhf(xw_cur.y + shi);

            // output (never re-read: no fence needed)
            *(float2*)pio = hv;

            // raw export (double-buffered, 2KB = 8 rows x 256B)
            *(float2*)(smem + EXP_OFF + (t & 1) * 2048 + er * 256 + ecp * 8) = hv;
        }

        // ---- exchange barrier: arrive, prefetch next xw, wait ----
        CLUSTER_ARRIVE();
        pio += HD;
        if (tid < 256 && t < TS - 1) xw_cur = *(const float2*)pio;
        CLUSTER_WAIT();

        // ---- pull all 8 ranks' raw exports into Hs (skip on final step) ----
        if (t < TS - 1) {
            uint32_t src = mapa_rank(
                sbase + EXP_OFF + (t & 1) * 2048 + prow * 256 + ppart * 32,
                prank);
            uint4 v0 = ld_cluster_v4(src);
            uint4 v1 = ld_cluster_v4(src + 16);
            *(uint2*)(pd)      = make_uint2(v0.x, v0.y);
            *(uint2*)(pd + 8)  = make_uint2(v0.z, v0.w);
            *(uint2*)(pd + 16) = make_uint2(v1.x, v1.y);
            *(uint2*)(pd + 24) = make_uint2(v1.z, v1.w);
        }
        __syncthreads();
    }
}

// ---------------------------------------------------------------------------
// Launch
// ---------------------------------------------------------------------------
extern "C" void kernel_launch(void* const* d_in, const int* in_sizes, int n_in,
                              void* d_out, int out_size) {
    (void)in_sizes; (void)n_in; (void)out_size;
    const float* x  = (const float*)d_in[0];   // [128, 512, 512]
    const float* h0 = (const float*)d_in[1];   // [128, 512]
    const float* Wx = (const float*)d_in[2];   // [512, 512]
    const float* Wh = (const float*)d_in[3];   // [512, 512]
    const float* b  = (const float*)d_in[4];   // [512]
    float* out = (float*)d_out;                // [128, 512, 512]

    dim3 gx(HD / 128, (NB * TS) / 128);        // (4, 512)
    xw_gemm<<<gx, 256>>>(x, Wx, b, out);

    cudaFuncSetAttribute(rnn_persistent,
                         cudaFuncAttributeMaxDynamicSharedMemorySize,
                         SMEM_RNN_BYTES);
    dim3 gs(8, NB / 8);                        // 8 CTAs/cluster x 16 clusters
    rnn_persistent<<<gs, 512, SMEM_RNN_BYTES>>>(Wh, h0, out);
}